// round 10
// baseline (speedup 1.0000x reference)
#include <cuda_runtime.h>
#include <math.h>
#include <stdint.h>

#define LDIM 32
#define NS   8          // samples per warp (MMA N dimension)

// hidden-state carry (row above): [block][col][row][sample], 128*32*64*8 floats = 8MB
__device__ float g_hp[128 * LDIM * 64 * NS];

__device__ __forceinline__ uint32_t f2tf(float f) {
    uint32_t r; asm("cvt.rna.tf32.f32 %0, %1;" : "=r"(r) : "f"(f)); return r;
}

// D += A * B  (m16n8k8 tf32)
__device__ __forceinline__ void mma_acc(float d[4], const uint32_t a[4],
                                        uint32_t b0, uint32_t b1) {
    asm volatile(
        "mma.sync.aligned.m16n8k8.row.col.f32.tf32.tf32.f32 "
        "{%0,%1,%2,%3}, {%4,%5,%6,%7}, {%8,%9}, {%0,%1,%2,%3};"
        : "+f"(d[0]), "+f"(d[1]), "+f"(d[2]), "+f"(d[3])
        : "r"(a[0]), "r"(a[1]), "r"(a[2]), "r"(a[3]), "r"(b0), "r"(b1));
}

// One warp per 8 samples. Step pre-activation for all 8 samples is one
// 64x72 @ 72x8 GEMM on tensor cores, computed in fp32-equivalent precision
// via the 3-term tf32 split: A_hi*B_hi + A_hi*B_lo + A_lo*B_hi.
// A_hi (k-tiles 0-7) in registers; A_lo and the ext k-tile in swizzled smem.
// u' = [h + carry_above ; onehot(left) ; onehot(up) ; 1] staged fp32 in smem,
// split hi/lo at read. Hp carry lives in a global scratch (L1-resident).
__global__ void __launch_bounds__(32, 1) rnn2d_kernel(
    const int*   __restrict__ x,     // (B, 32, 32)
    const float* __restrict__ Win,   // (2, 64)
    const float* __restrict__ Wc,    // (64, 64)
    const float* __restrict__ bc,    // (64,)
    const float* __restrict__ Wout,  // (64, 2)
    const float* __restrict__ bout,  // (2,)
    float*       __restrict__ out)   // (B,)
{
    const int b    = blockIdx.x;
    const int lane = threadIdx.x;
    const int g    = lane >> 2;     // 0..7 : D-rows g,g+8 / B n-col (sample)
    const int q4   = lane & 3;      // 0..3 : A/B k-col, D sample-cols 2q4,2q4+1

    __shared__ __align__(16) float usm[2][NS][84];   // u' fp32, padded stride 84
    __shared__ int   xsm[2][NS][LDIM];
    __shared__ uint4 aloS[36 * 32];                  // A_lo fragments, swizzled
    __shared__ uint4 ahiE[4 * 32];                   // A_hi ext-tile fragments

    // ---------------- build A fragments ----------------
    // A(row, col): col<64 -> Wc[col][row]; ext cols 64..71:
    //   [Win0, Win1, Win0, Win1, bc, 0, 0, 0]
    uint32_t wa[32][4];   // k-tiles 0..7 A_hi
#pragma unroll
    for (int kt = 0; kt < 9; ++kt) {
#pragma unroll
        for (int m = 0; m < 4; ++m) {
            const int tile = kt * 4 + m;
            const int r0 = 16 * m + g, r1 = r0 + 8;
            const int k0 = 8 * kt + q4, k1 = k0 + 4;
            float w[4];
#pragma unroll
            for (int e = 0; e < 4; ++e) {
                const int r = (e & 1) ? r1 : r0;
                const int k = (e & 2) ? k1 : k0;
                float v;
                if (k < 64)       v = Wc[k * 64 + r];
                else {
                    const int ek = k - 64;
                    if (ek == 0 || ek == 2)      v = Win[r];
                    else if (ek == 1 || ek == 3) v = Win[64 + r];
                    else if (ek == 4)            v = bc[r];
                    else                         v = 0.0f;
                }
                w[e] = v;
            }
            uint32_t hi[4], lo[4];
#pragma unroll
            for (int e = 0; e < 4; ++e) {
                hi[e] = f2tf(w[e]);
                lo[e] = f2tf(w[e] - __uint_as_float(hi[e]));
            }
            aloS[tile * 32 + lane] = make_uint4(lo[0], lo[1], lo[2], lo[3]);
            if (kt < 8) {
                wa[tile][0] = hi[0]; wa[tile][1] = hi[1];
                wa[tile][2] = hi[2]; wa[tile][3] = hi[3];
            } else {
                ahiE[m * 32 + lane] = make_uint4(hi[0], hi[1], hi[2], hi[3]);
            }
        }
    }

    float wod[8];
#pragma unroll
    for (int m = 0; m < 4; ++m) {
        const int r0 = 16 * m + g, r1 = r0 + 8;
        wod[2 * m]     = Wout[r0 * 2] - Wout[r0 * 2 + 1];
        wod[2 * m + 1] = Wout[r1 * 2] - Wout[r1 * 2 + 1];
    }
    const float bod = bout[0] - bout[1];

    // init staging parity 0 (u=0, ext zeros + bias) and xsm[1]=0
    for (int idx = lane; idx < NS * 84; idx += 32) ((float*)usm[0])[idx] = 0.0f;
    for (int idx = lane; idx < NS * LDIM; idx += 32) ((int*)xsm[1])[idx] = 0;
    __syncwarp();
    if (lane < NS) usm[0][lane][68] = 1.0f;   // bias row (ext col 4)

    float* hpB = g_hp + (size_t)b * (LDIM * 64 * NS);
    const int* xb = x + (size_t)(NS * b) * LDIM * LDIM;

    float logp0 = 0.0f, logp1 = 0.0f;
    float pd0 = 0.0f, pd1 = 0.0f;
    int   ppx0 = 0, ppx1 = 0;
    float pend = 0.0f;

    for (int i = 0; i < LDIM; ++i) {
#pragma unroll
        for (int s = 0; s < NS; ++s)
            xsm[i & 1][s][lane] = xb[s * LDIM * LDIM + i * LDIM + lane];

        const int dir  = (i & 1) ? -1 : 1;
        const int cur  = i & 1;
        const int prev = cur ^ 1;

#pragma unroll 1
        for (int jj = 0; jj < LDIM; ++jj) {
            const int c   = (i & 1) ? (LDIM - 1 - jj) : jj;
            const int cnc = (jj < LDIM - 1) ? (c + dir) : c;
            const int p   = jj & 1;

            __syncwarp();

            // ---- deferred softmax of previous step (overlaps MMAs) ----
            {
                float d0 = pd0, d1 = pd1;
#pragma unroll
                for (int off = 4; off <= 16; off <<= 1) {
                    d0 += __shfl_xor_sync(0xffffffffu, d0, off);
                    d1 += __shfl_xor_sync(0xffffffffu, d1, off);
                }
                d0 += bod; d1 += bod;
                const float v0 = ppx0 ? d0 : -d0;
                const float v1 = ppx1 ? d1 : -d1;
                float lp0 = -(fmaxf(v0, 0.0f) + __logf(1.0f + __expf(-fabsf(v0))));
                float lp1 = -(fmaxf(v1, 0.0f) + __logf(1.0f + __expf(-fabsf(v1))));
                if (lp0 != lp0) lp0 = -35.0f;
                if (lp1 != lp1) lp1 = -35.0f;
                logp0 += pend * lp0;
                logp1 += pend * lp1;
            }

            // ---- batched GEMM: 3-term split, 3 independent accum sets ----
            float D1[4][4], Dc1[4][4], Dc2[4][4];
#pragma unroll
            for (int m = 0; m < 4; ++m)
#pragma unroll
                for (int e = 0; e < 4; ++e) {
                    D1[m][e] = 0.0f; Dc1[m][e] = 0.0f; Dc2[m][e] = 0.0f;
                }

#pragma unroll
            for (int kt = 0; kt < 9; ++kt) {
                const float u0 = usm[p][g][8 * kt + q4];
                const float u1 = usm[p][g][8 * kt + q4 + 4];
                const uint32_t bh0 = f2tf(u0);
                const uint32_t bh1 = f2tf(u1);
                const uint32_t bl0 = f2tf(u0 - __uint_as_float(bh0));
                const uint32_t bl1 = f2tf(u1 - __uint_as_float(bh1));
#pragma unroll
                for (int m = 0; m < 4; ++m) {
                    const int tile = kt * 4 + m;
                    uint32_t ahi[4];
                    if (kt < 8) {
                        ahi[0] = wa[tile][0]; ahi[1] = wa[tile][1];
                        ahi[2] = wa[tile][2]; ahi[3] = wa[tile][3];
                    } else {
                        const uint4 h4 = ahiE[m * 32 + lane];
                        ahi[0] = h4.x; ahi[1] = h4.y; ahi[2] = h4.z; ahi[3] = h4.w;
                    }
                    mma_acc(D1[m],  ahi, bh0, bh1);          // A_hi * B_hi
                    mma_acc(Dc1[m], ahi, bl0, bl1);          // A_hi * B_lo
                    const uint4 l4 = aloS[tile * 32 + lane];
                    uint32_t alo[4] = {l4.x, l4.y, l4.z, l4.w};
                    mma_acc(Dc2[m], alo, bh0, bh1);          // A_lo * B_hi
                }
            }

            // ---- carry-from-above loads (L1-resident global scratch) ----
            float hpv[16];
            const float* hpc = hpB + cnc * (64 * NS);
#pragma unroll
            for (int m = 0; m < 4; ++m) {
                const int r0 = 16 * m + g, r1 = r0 + 8;
                hpv[4 * m + 0] = hpc[r0 * NS + 2 * q4];
                hpv[4 * m + 1] = hpc[r0 * NS + 2 * q4 + 1];
                hpv[4 * m + 2] = hpc[r1 * NS + 2 * q4];
                hpv[4 * m + 3] = hpc[r1 * NS + 2 * q4 + 1];
            }
            const bool gate = (jj < LDIM - 1) && (i > 0);

            const int px0 = xsm[cur][2 * q4][c];
            const int px1 = xsm[cur][2 * q4 + 1][c];

            // ---- elu + softmax partials + staging ----
            float npd0 = 0.0f, npd1 = 0.0f;
            float* hpw = hpB + c * (64 * NS);
#pragma unroll
            for (int m = 0; m < 4; ++m) {
                const int r0 = 16 * m + g, r1 = r0 + 8;
                float y, n00, n01, n10, n11;
                y = D1[m][0] + Dc1[m][0] + Dc2[m][0];
                n00 = (y > 0.0f) ? y : (__expf(y) - 1.0f);
                y = D1[m][1] + Dc1[m][1] + Dc2[m][1];
                n01 = (y > 0.0f) ? y : (__expf(y) - 1.0f);
                y = D1[m][2] + Dc1[m][2] + Dc2[m][2];
                n10 = (y > 0.0f) ? y : (__expf(y) - 1.0f);
                y = D1[m][3] + Dc1[m][3] + Dc2[m][3];
                n11 = (y > 0.0f) ? y : (__expf(y) - 1.0f);

                npd0 = fmaf(n00, wod[2 * m], fmaf(n10, wod[2 * m + 1], npd0));
                npd1 = fmaf(n01, wod[2 * m], fmaf(n11, wod[2 * m + 1], npd1));

                usm[p ^ 1][2 * q4][r0]     = n00 + (gate ? hpv[4 * m + 0] : 0.0f);
                usm[p ^ 1][2 * q4 + 1][r0] = n01 + (gate ? hpv[4 * m + 1] : 0.0f);
                usm[p ^ 1][2 * q4][r1]     = n10 + (gate ? hpv[4 * m + 2] : 0.0f);
                usm[p ^ 1][2 * q4 + 1][r1] = n11 + (gate ? hpv[4 * m + 3] : 0.0f);

                hpw[r0 * NS + 2 * q4]     = n00;
                hpw[r0 * NS + 2 * q4 + 1] = n01;
                hpw[r1 * NS + 2 * q4]     = n10;
                hpw[r1 * NS + 2 * q4 + 1] = n11;
            }
            pd0 = npd0;  pd1 = npd1;
            ppx0 = px0;  ppx1 = px1;
            pend = 1.0f;

            // ---- ext tile for next step (lanes 0..7, one per sample) ----
            if (lane < NS) {
                const int s  = lane;
                const int xc = xsm[cur][s][c];
                float l0, l1, u0, u1;
                if (jj < LDIM - 1) {
                    l0 = xc ? 0.0f : 1.0f;  l1 = xc ? 1.0f : 0.0f;
                    const int xu = (i > 0) ? xsm[prev][s][cnc] : 0;
                    u0 = (i > 0) ? (xu ? 0.0f : 1.0f) : 0.0f;
                    u1 = (i > 0) ? (xu ? 1.0f : 0.0f) : 0.0f;
                } else {
                    l0 = 0.0f; l1 = 0.0f;                 // next row: no left
                    u0 = xc ? 0.0f : 1.0f;  u1 = xc ? 1.0f : 0.0f;  // up = this x
                }
                float4* dst = (float4*)&usm[p ^ 1][s][64];
                dst[0] = make_float4(l0, l1, u0, u1);
                dst[1] = make_float4(1.0f, 0.0f, 0.0f, 0.0f);
            }
        }
    }

    // ---- flush the final pending step ----
    {
        float d0 = pd0, d1 = pd1;
#pragma unroll
        for (int off = 4; off <= 16; off <<= 1) {
            d0 += __shfl_xor_sync(0xffffffffu, d0, off);
            d1 += __shfl_xor_sync(0xffffffffu, d1, off);
        }
        d0 += bod; d1 += bod;
        const float v0 = ppx0 ? d0 : -d0;
        const float v1 = ppx1 ? d1 : -d1;
        float lp0 = -(fmaxf(v0, 0.0f) + __logf(1.0f + __expf(-fabsf(v0))));
        float lp1 = -(fmaxf(v1, 0.0f) + __logf(1.0f + __expf(-fabsf(v1))));
        if (lp0 != lp0) lp0 = -35.0f;
        if (lp1 != lp1) lp1 = -35.0f;
        logp0 += pend * lp0;
        logp1 += pend * lp1;
    }

    if (g == 0) {
        out[NS * b + 2 * q4]     = 0.5f * logp0;
        out[NS * b + 2 * q4 + 1] = 0.5f * logp1;
    }
}

extern "C" void kernel_launch(void* const* d_in, const int* in_sizes, int n_in,
                              void* d_out, int out_size) {
    const int*   x    = (const int*)  d_in[0];
    const float* Win  = (const float*)d_in[1];
    const float* Wc   = (const float*)d_in[2];
    const float* bc   = (const float*)d_in[3];
    const float* Wout = (const float*)d_in[4];
    const float* bout = (const float*)d_in[5];
    float* out = (float*)d_out;

    const int B = in_sizes[0] / (LDIM * LDIM);
    rnn2d_kernel<<<B / NS, 32>>>(x, Win, Wc, bc, Wout, bout, out);
}

// round 12
// speedup vs baseline: 2.2443x; 2.2443x over previous
#include <cuda_runtime.h>
#include <math.h>
#include <stdint.h>

#define LDIM 32
#define HDIM 64

typedef unsigned long long ull;

__device__ __forceinline__ ull pack2(float lo, float hi) {
    ull r; asm("mov.b64 %0, {%1, %2};" : "=l"(r) : "f"(lo), "f"(hi)); return r;
}
__device__ __forceinline__ float2 unpack2(ull v) {
    float2 r; asm("mov.b64 {%0, %1}, %2;" : "=f"(r.x), "=f"(r.y) : "l"(v)); return r;
}
#define FMA2(d, a, b, c) \
    asm("fma.rn.f32x2 %0, %1, %2, %3;" : "=l"(d) : "l"(a), "l"(b), "l"(c))
#define ADD2(d, a, b) \
    asm("add.rn.f32x2 %0, %1, %2;" : "=l"(d) : "l"(a), "l"(b))

// One warp per sample. Thread t owns channels {t, t+32}.
// u broadcast via double-buffered smem (2 STS + 16 broadcast LDS.128),
// ONE syncwarp per step. x rows live in registers (shfl broadcast).
// Softmax: the signed logit-difference partial (sign=xC, bod folded in) is
// PARTIALLY reduced in-loop with just 3 butterfly shfls (32 -> 4 groups,
// deferred one step to overlap the matvec) and stored to a smem table.
// ALL softplus/log/exp work runs once in a parallel epilogue.
__global__ void __launch_bounds__(32, 1) rnn2d_kernel(
    const int*   __restrict__ x,     // (B, 32, 32) int32, values in {0,1}
    const float* __restrict__ Win,   // (2, 64)
    const float* __restrict__ Wc,    // (64, 64)
    const float* __restrict__ bc,    // (64,)
    const float* __restrict__ Wout,  // (64, 2)
    const float* __restrict__ bout,  // (2,)
    float*       __restrict__ out)   // (B,)
{
    const int b = blockIdx.x;
    const int t = threadIdx.x;          // 0..31

    __shared__ float2 Hprev2[LDIM][LDIM];           // [col][t] thread-private
    __shared__ __align__(16) float ubuf[2][HDIM];   // double-buffered u (k-order)
    __shared__ __align__(16) float vbuf[4 * 1025];  // 4 group partials / step
                                                    // step s lives at 4*(s+1)

    // ---- weights: columns j0=t, j1=t+32 packed along k ----
    ull wcp0[HDIM / 2], wcp1[HDIM / 2];
#pragma unroll
    for (int k = 0; k < HDIM / 2; ++k) {
        wcp0[k] = pack2(Wc[(2 * k) * HDIM + t],      Wc[(2 * k + 1) * HDIM + t]);
        wcp1[k] = pack2(Wc[(2 * k) * HDIM + t + 32], Wc[(2 * k + 1) * HDIM + t + 32]);
    }
    const float win00 = Win[t],      win10 = Win[HDIM + t];
    const float win01 = Win[t + 32], win11 = Win[HDIM + t + 32];
    const float bc0   = bc[t],       bc1   = bc[t + 32];
    const float wod0  = Wout[t * 2]        - Wout[t * 2 + 1];
    const float wod1  = Wout[(t + 32) * 2] - Wout[(t + 32) * 2 + 1];
    const float bodt  = (t == 0) ? (bout[0] - bout[1]) : 0.0f;

#pragma unroll
    for (int c = 0; c < LDIM; ++c) Hprev2[c][t] = make_float2(0.0f, 0.0f);

    const int* xb = x + (size_t)b * LDIM * LDIM;

    float2 hp  = make_float2(0.0f, 0.0f);
    float  ppd = 0.0f;                  // deferred signed partial (step j-1)

    int xv     = xb[t];                 // row 0 (this thread's column)
    int xvPrev = 0;

    for (int i = 0; i < LDIM; ++i) {
        const int xvNext = xb[((i < LDIM - 1) ? (i + 1) : (LDIM - 1)) * LDIM + t];
        const int dir = (i & 1) ? -1 : 1;

        float h0 = 0.0f, h1 = 0.0f;
        int   xL = 0;

#pragma unroll 4
        for (int jj = 0; jj < LDIM; ++jj) {
            const int c = (i & 1) ? (LDIM - 1 - jj) : jj;
            const int p = jj & 1;
            const int n = i * LDIM + jj;     // global step index

            // stage u = h + carry-from-above (hp prefetched, thread-private)
            ubuf[p][t]      = h0 + hp.x;
            ubuf[p][t + 32] = h1 + hp.y;

            // base = bc + newR @ Win (off the recurrence chain)
            float r0 = bc0, r1 = bc1;
            if (jj > 0) { r0 += xL ? win10 : win00;  r1 += xL ? win11 : win01; }
            if (i  > 0) {
                const int xU = __shfl_sync(0xffffffffu, xvPrev, c);
                r0 += xU ? win10 : win00;  r1 += xU ? win11 : win01;
            }
            const int xC = __shfl_sync(0xffffffffu, xv, c);

            __syncwarp();

            // ---- partial reduction of step j-1 (3 shfls, overlaps matvec) ----
            {
                float dp = ppd;
                dp += __shfl_xor_sync(0xffffffffu, dp, 16);
                dp += __shfl_xor_sync(0xffffffffu, dp, 8);
                dp += __shfl_xor_sync(0xffffffffu, dp, 4);
                if (t < 4) vbuf[4 * n + t] = dp;   // slot for step n-1
            }

            // ---- 64-wide matvec, packed f32x2 FMAs ----
            ull a00 = pack2(r0, 0.0f), a01 = 0;
            ull a10 = pack2(r1, 0.0f), a11 = 0;
            const ulonglong2* up = (const ulonglong2*)ubuf[p];
#pragma unroll
            for (int k = 0; k < HDIM / 4; ++k) {
                const ulonglong2 uv = up[k];
                FMA2(a00, uv.x, wcp0[2 * k],     a00);
                FMA2(a10, uv.x, wcp1[2 * k],     a10);
                FMA2(a01, uv.y, wcp0[2 * k + 1], a01);
                FMA2(a11, uv.y, wcp1[2 * k + 1], a11);
            }
            ull as0, as1;
            ADD2(as0, a00, a01);
            ADD2(as1, a10, a11);
            const float2 f0 = unpack2(as0);
            const float2 f1 = unpack2(as1);
            const float s0 = f0.x + f0.y;
            const float s1 = f1.x + f1.y;

            // elu (alpha = 1)
            const float nh0 = (s0 > 0.0f) ? s0 : (__expf(s0) - 1.0f);
            const float nh1 = (s1 > 0.0f) ? s1 : (__expf(s1) - 1.0f);

            // signed softmax partial for this step (sign = xC, bod folded)
            {
                const float base = nh0 * wod0 + nh1 * wod1 + bodt;
                ppd = xC ? base : -base;
            }

            // writeback + prefetch next carry-from-above (thread-private)
            Hprev2[c][t] = make_float2(nh0, nh1);
            const int cn = (jj < LDIM - 1) ? (c + dir) : c;  // next row: same col
            hp = Hprev2[cn][t];

            h0 = nh0;
            h1 = nh1;
            xL = xC;
        }

        xvPrev = xv;
        xv     = xvNext;
    }

    // ---- flush the final step's partials ----
    {
        float dp = ppd;
        dp += __shfl_xor_sync(0xffffffffu, dp, 16);
        dp += __shfl_xor_sync(0xffffffffu, dp, 8);
        dp += __shfl_xor_sync(0xffffffffu, dp, 4);
        if (t < 4) vbuf[4 * 1024 + t] = dp;
    }
    __syncwarp();

    // ---- epilogue: 1024 softplus terms, 32 per lane, conflict-free ----
    float acc = 0.0f;
#pragma unroll 4
    for (int k = 0; k < LDIM; ++k) {
        const int s = k * LDIM + t;
        const float4 v4 = *(const float4*)&vbuf[4 * (s + 1)];
        const float v   = (v4.x + v4.y) + (v4.z + v4.w);
        const float sp  = fmaxf(v, 0.0f) + __logf(1.0f + __expf(-fabsf(v)));
        acc += (sp != sp) ? -35.0f : -sp;
    }
#pragma unroll
    for (int off = 16; off > 0; off >>= 1)
        acc += __shfl_xor_sync(0xffffffffu, acc, off);

    if (t == 0) out[b] = 0.5f * acc;
}

extern "C" void kernel_launch(void* const* d_in, const int* in_sizes, int n_in,
                              void* d_out, int out_size) {
    const int*   x    = (const int*)  d_in[0];
    const float* Win  = (const float*)d_in[1];
    const float* Wc   = (const float*)d_in[2];
    const float* bc   = (const float*)d_in[3];
    const float* Wout = (const float*)d_in[4];
    const float* bout = (const float*)d_in[5];
    float* out = (float*)d_out;

    const int B = in_sizes[0] / (LDIM * LDIM);
    rnn2d_kernel<<<B, 32>>>(x, Win, Wc, bc, Wout, bout, out);
}

// round 13
// speedup vs baseline: 3.6800x; 1.6397x over previous
#include <cuda_runtime.h>
#include <math.h>
#include <stdint.h>

#define LDIM 32
#define HDIM 64

typedef unsigned long long ull;

__device__ __forceinline__ ull pack2(float lo, float hi) {
    ull r; asm("mov.b64 %0, {%1, %2};" : "=l"(r) : "f"(lo), "f"(hi)); return r;
}
__device__ __forceinline__ float2 unpack2(ull v) {
    float2 r; asm("mov.b64 {%0, %1}, %2;" : "=f"(r.x), "=f"(r.y) : "l"(v)); return r;
}
#define FMA2(d, a, b, c) \
    asm("fma.rn.f32x2 %0, %1, %2, %3;" : "=l"(d) : "l"(a), "l"(b), "l"(c))
#define ADD2(d, a, b) \
    asm("add.rn.f32x2 %0, %1, %2;" : "=l"(d) : "l"(a), "l"(b))

// One warp per sample. Thread t owns channels {t, t+32}.
// u broadcast via double-buffered smem, ONE syncwarp per step, x rows in
// registers (shfl broadcast). Softmax: signed logit-diff partials are
// 3-shfl partially reduced (every lane then holds its group-of-4 sum) and
// stored to a smem table with a BRANCH-FREE address-selected STS (lanes
// 4..31 write a dummy line — no BSSY/BSYNC in the hot loop). All
// softplus/log/exp work runs once in a parallel epilogue.
__global__ void __launch_bounds__(32, 1) rnn2d_kernel(
    const int*   __restrict__ x,     // (B, 32, 32) int32, values in {0,1}
    const float* __restrict__ Win,   // (2, 64)
    const float* __restrict__ Wc,    // (64, 64)
    const float* __restrict__ bc,    // (64,)
    const float* __restrict__ Wout,  // (64, 2)
    const float* __restrict__ bout,  // (2,)
    float*       __restrict__ out)   // (B,)
{
    const int b = blockIdx.x;
    const int t = threadIdx.x;          // 0..31

    __shared__ float2 Hprev2[LDIM][LDIM];           // [col][t] thread-private
    __shared__ __align__(16) float ubuf[2][HDIM];   // double-buffered u (k-order)
    __shared__ __align__(16) float vbuf[4 * 1025];  // 4 group partials / step
    __shared__ float dump[32];                      // sink for lanes 4..31

    // ---- weights: columns j0=t, j1=t+32 packed along k ----
    ull wcp0[HDIM / 2], wcp1[HDIM / 2];
#pragma unroll
    for (int k = 0; k < HDIM / 2; ++k) {
        wcp0[k] = pack2(Wc[(2 * k) * HDIM + t],      Wc[(2 * k + 1) * HDIM + t]);
        wcp1[k] = pack2(Wc[(2 * k) * HDIM + t + 32], Wc[(2 * k + 1) * HDIM + t + 32]);
    }
    const float win00 = Win[t],      win10 = Win[HDIM + t];
    const float win01 = Win[t + 32], win11 = Win[HDIM + t + 32];
    const float bc0   = bc[t],       bc1   = bc[t + 32];
    const float wod0  = Wout[t * 2]        - Wout[t * 2 + 1];
    const float wod1  = Wout[(t + 32) * 2] - Wout[(t + 32) * 2 + 1];
    const float bodt  = (t == 0) ? (bout[0] - bout[1]) : 0.0f;

#pragma unroll
    for (int c = 0; c < LDIM; ++c) Hprev2[c][t] = make_float2(0.0f, 0.0f);

    const int* xb = x + (size_t)b * LDIM * LDIM;

    float2 hp  = make_float2(0.0f, 0.0f);
    float  ppd = 0.0f;                  // deferred signed partial (step j-1)

    int xv     = xb[t];                 // row 0 (this thread's column)
    int xvPrev = 0;

    for (int i = 0; i < LDIM; ++i) {
        const int xvNext = xb[((i < LDIM - 1) ? (i + 1) : (LDIM - 1)) * LDIM + t];
        const int dir = (i & 1) ? -1 : 1;

        float h0 = 0.0f, h1 = 0.0f;
        int   xL = 0;

#pragma unroll 4
        for (int jj = 0; jj < LDIM; ++jj) {
            const int c = (i & 1) ? (LDIM - 1 - jj) : jj;
            const int p = jj & 1;
            const int n = i * LDIM + jj;     // global step index

            // stage u = h + carry-from-above (hp prefetched, thread-private)
            ubuf[p][t]      = h0 + hp.x;
            ubuf[p][t + 32] = h1 + hp.y;

            // base = bc + newR @ Win (off the recurrence chain)
            float r0 = bc0, r1 = bc1;
            if (jj > 0) { r0 += xL ? win10 : win00;  r1 += xL ? win11 : win01; }
            if (i  > 0) {
                const int xU = __shfl_sync(0xffffffffu, xvPrev, c);
                r0 += xU ? win10 : win00;  r1 += xU ? win11 : win01;
            }
            const int xC = __shfl_sync(0xffffffffu, xv, c);

            __syncwarp();

            // ---- partial reduction of step j-1 (3 shfls, overlaps matvec);
            //      branch-free STS: every lane stores, only lanes 0-3 land ----
            {
                float dp = ppd;
                dp += __shfl_xor_sync(0xffffffffu, dp, 16);
                dp += __shfl_xor_sync(0xffffffffu, dp, 8);
                dp += __shfl_xor_sync(0xffffffffu, dp, 4);
                float* dst = (t < 4) ? &vbuf[4 * n + t] : &dump[t];
                *dst = dp;
            }

            // ---- 64-wide matvec, packed f32x2 FMAs ----
            ull a00 = pack2(r0, 0.0f), a01 = 0;
            ull a10 = pack2(r1, 0.0f), a11 = 0;
            const ulonglong2* up = (const ulonglong2*)ubuf[p];
#pragma unroll
            for (int k = 0; k < HDIM / 4; ++k) {
                const ulonglong2 uv = up[k];
                FMA2(a00, uv.x, wcp0[2 * k],     a00);
                FMA2(a10, uv.x, wcp1[2 * k],     a10);
                FMA2(a01, uv.y, wcp0[2 * k + 1], a01);
                FMA2(a11, uv.y, wcp1[2 * k + 1], a11);
            }
            ull as0, as1;
            ADD2(as0, a00, a01);
            ADD2(as1, a10, a11);
            const float2 f0 = unpack2(as0);
            const float2 f1 = unpack2(as1);
            const float s0 = f0.x + f0.y;
            const float s1 = f1.x + f1.y;

            // elu (alpha = 1)
            const float nh0 = (s0 > 0.0f) ? s0 : (__expf(s0) - 1.0f);
            const float nh1 = (s1 > 0.0f) ? s1 : (__expf(s1) - 1.0f);

            // signed softmax partial for this step (sign = xC, bod folded)
            {
                const float base = nh0 * wod0 + nh1 * wod1 + bodt;
                ppd = xC ? base : -base;
            }

            // writeback + prefetch next carry-from-above (thread-private)
            Hprev2[c][t] = make_float2(nh0, nh1);
            const int cn = (jj < LDIM - 1) ? (c + dir) : c;  // next row: same col
            hp = Hprev2[cn][t];

            h0 = nh0;
            h1 = nh1;
            xL = xC;
        }

        xvPrev = xv;
        xv     = xvNext;
    }

    // ---- flush the final step's partials (branch-free as well) ----
    {
        float dp = ppd;
        dp += __shfl_xor_sync(0xffffffffu, dp, 16);
        dp += __shfl_xor_sync(0xffffffffu, dp, 8);
        dp += __shfl_xor_sync(0xffffffffu, dp, 4);
        float* dst = (t < 4) ? &vbuf[4 * 1024 + t] : &dump[t];
        *dst = dp;
    }
    __syncwarp();

    // ---- epilogue: 1024 softplus terms, 32 per lane, conflict-free ----
    float acc = 0.0f;
#pragma unroll 4
    for (int k = 0; k < LDIM; ++k) {
        const int s = k * LDIM + t;
        const float4 v4 = *(const float4*)&vbuf[4 * (s + 1)];
        const float v   = (v4.x + v4.y) + (v4.z + v4.w);
        const float sp  = fmaxf(v, 0.0f) + __logf(1.0f + __expf(-fabsf(v)));
        acc += (sp != sp) ? -35.0f : -sp;
    }
#pragma unroll
    for (int off = 16; off > 0; off >>= 1)
        acc += __shfl_xor_sync(0xffffffffu, acc, off);

    if (t == 0) out[b] = 0.5f * acc;
}

extern "C" void kernel_launch(void* const* d_in, const int* in_sizes, int n_in,
                              void* d_out, int out_size) {
    const int*   x    = (const int*)  d_in[0];
    const float* Win  = (const float*)d_in[1];
    const float* Wc   = (const float*)d_in[2];
    const float* bc   = (const float*)d_in[3];
    const float* Wout = (const float*)d_in[4];
    const float* bout = (const float*)d_in[5];
    float* out = (float*)d_out;

    const int B = in_sizes[0] / (LDIM * LDIM);
    rnn2d_kernel<<<B, 32>>>(x, Win, Wc, bc, Wout, bout, out);
}

// round 14
// speedup vs baseline: 3.9092x; 1.0623x over previous
#include <cuda_runtime.h>
#include <math.h>
#include <stdint.h>

#define LDIM 32
#define HDIM 64

typedef unsigned long long ull;

__device__ __forceinline__ ull pack2(float lo, float hi) {
    ull r; asm("mov.b64 %0, {%1, %2};" : "=l"(r) : "f"(lo), "f"(hi)); return r;
}
__device__ __forceinline__ float2 unpack2(ull v) {
    float2 r; asm("mov.b64 {%0, %1}, %2;" : "=f"(r.x), "=f"(r.y) : "l"(v)); return r;
}
#define FMA2(d, a, b, c) \
    asm("fma.rn.f32x2 %0, %1, %2, %3;" : "=l"(d) : "l"(a), "l"(b), "l"(c))
#define ADD2(d, a, b) \
    asm("add.rn.f32x2 %0, %1, %2;" : "=l"(d) : "l"(a), "l"(b))

// One warp per sample. Thread t owns ADJACENT channels {2t, 2t+1} so the u
// staging is a single STS.64. u broadcast via double-buffered smem, ONE
// syncwarp per step; current+previous x rows are packed 2 bits/column into
// one register so ONE shfl yields both xC and xU. Softmax: signed logit-diff
// partials are 3-shfl partially reduced and stored with a branch-free
// address-selected STS; all softplus/log/exp runs once in the epilogue.
__global__ void __launch_bounds__(32, 1) rnn2d_kernel(
    const int*   __restrict__ x,     // (B, 32, 32) int32, values in {0,1}
    const float* __restrict__ Win,   // (2, 64)
    const float* __restrict__ Wc,    // (64, 64)
    const float* __restrict__ bc,    // (64,)
    const float* __restrict__ Wout,  // (64, 2)
    const float* __restrict__ bout,  // (2,)
    float*       __restrict__ out)   // (B,)
{
    const int b  = blockIdx.x;
    const int t  = threadIdx.x;         // 0..31
    const int c0 = 2 * t, c1 = 2 * t + 1;

    __shared__ float2 Hprev2[LDIM][LDIM];           // [col][t] thread-private
    __shared__ __align__(16) float ubuf[2][HDIM];   // double-buffered u (channel order)
    __shared__ __align__(16) float vbuf[4 * 1025];  // 4 group partials / step
    __shared__ float dump[32];                      // sink for lanes 4..31

    // ---- weights: columns c0, c1 packed along k ----
    ull wcp0[HDIM / 2], wcp1[HDIM / 2];
#pragma unroll
    for (int k = 0; k < HDIM / 2; ++k) {
        wcp0[k] = pack2(Wc[(2 * k) * HDIM + c0], Wc[(2 * k + 1) * HDIM + c0]);
        wcp1[k] = pack2(Wc[(2 * k) * HDIM + c1], Wc[(2 * k + 1) * HDIM + c1]);
    }
    const float win00 = Win[c0], win10 = Win[HDIM + c0];
    const float win01 = Win[c1], win11 = Win[HDIM + c1];
    const float bc0   = bc[c0],  bc1   = bc[c1];
    const float wod0  = Wout[c0 * 2] - Wout[c0 * 2 + 1];
    const float wod1  = Wout[c1 * 2] - Wout[c1 * 2 + 1];
    const float bodt  = (t == 0) ? (bout[0] - bout[1]) : 0.0f;

#pragma unroll
    for (int c = 0; c < LDIM; ++c) Hprev2[c][t] = make_float2(0.0f, 0.0f);

    const int* xb = x + (size_t)b * LDIM * LDIM;

    float2 hp  = make_float2(0.0f, 0.0f);
    float  ppd = 0.0f;                  // deferred signed partial (step j-1)

    int xv = xb[t];                     // row 0 (this thread's column), in {0,1}

    for (int i = 0; i < LDIM; ++i) {
        const int xvNext = xb[((i < LDIM - 1) ? (i + 1) : (LDIM - 1)) * LDIM + t];
        const int dir = (i & 1) ? -1 : 1;
        const int xp  = xv;             // bit0 = current row, bit1 = previous row
                                        // (packed below at row rotation)

        float h0 = 0.0f, h1 = 0.0f;
        int   xL = 0;

#pragma unroll 4
        for (int jj = 0; jj < LDIM; ++jj) {
            const int c = (i & 1) ? (LDIM - 1 - jj) : jj;
            const int p = jj & 1;
            const int n = i * LDIM + jj;     // global step index

            // stage u = h + carry-from-above as ONE 64-bit store
            *(ull*)&ubuf[p][c0] = pack2(h0 + hp.x, h1 + hp.y);

            // one shfl -> both current (bit0) and above (bit1) x values
            const int xs = __shfl_sync(0xffffffffu, xp, c);
            const int xC = xs & 1;
            const int xU = xs >> 1;

            // base = bc + newR @ Win (off the recurrence chain)
            float r0 = bc0, r1 = bc1;
            if (jj > 0) { r0 += xL ? win10 : win00;  r1 += xL ? win11 : win01; }
            if (i  > 0) { r0 += xU ? win10 : win00;  r1 += xU ? win11 : win01; }

            __syncwarp();

            // ---- partial reduction of step j-1 (3 shfls, overlaps matvec);
            //      branch-free STS: every lane stores, only lanes 0-3 land ----
            {
                float dp = ppd;
                dp += __shfl_xor_sync(0xffffffffu, dp, 16);
                dp += __shfl_xor_sync(0xffffffffu, dp, 8);
                dp += __shfl_xor_sync(0xffffffffu, dp, 4);
                float* dst = (t < 4) ? &vbuf[4 * n + t] : &dump[t];
                *dst = dp;
            }

            // ---- 64-wide matvec, packed f32x2 FMAs ----
            ull a00 = pack2(r0, 0.0f), a01 = 0;
            ull a10 = pack2(r1, 0.0f), a11 = 0;
            const ulonglong2* up = (const ulonglong2*)ubuf[p];
#pragma unroll
            for (int k = 0; k < HDIM / 4; ++k) {
                const ulonglong2 uv = up[k];
                FMA2(a00, uv.x, wcp0[2 * k],     a00);
                FMA2(a10, uv.x, wcp1[2 * k],     a10);
                FMA2(a01, uv.y, wcp0[2 * k + 1], a01);
                FMA2(a11, uv.y, wcp1[2 * k + 1], a11);
            }
            ull as0, as1;
            ADD2(as0, a00, a01);
            ADD2(as1, a10, a11);
            const float2 f0 = unpack2(as0);
            const float2 f1 = unpack2(as1);
            const float s0 = f0.x + f0.y;
            const float s1 = f1.x + f1.y;

            // elu (alpha = 1)
            const float nh0 = (s0 > 0.0f) ? s0 : (__expf(s0) - 1.0f);
            const float nh1 = (s1 > 0.0f) ? s1 : (__expf(s1) - 1.0f);

            // signed softmax partial for this step (sign = xC, bod folded)
            {
                const float base = nh0 * wod0 + nh1 * wod1 + bodt;
                ppd = xC ? base : -base;
            }

            // writeback + prefetch next carry-from-above (thread-private)
            Hprev2[c][t] = make_float2(nh0, nh1);
            const int cn = (jj < LDIM - 1) ? (c + dir) : c;  // next row: same col
            hp = Hprev2[cn][t];

            h0 = nh0;
            h1 = nh1;
            xL = xC;
        }

        // rotate rows: new packed x = next row (bit0) | this row shifted up (bit1)
        xv = xvNext | ((xp & 1) << 1);
    }

    // ---- flush the final step's partials (branch-free as well) ----
    {
        float dp = ppd;
        dp += __shfl_xor_sync(0xffffffffu, dp, 16);
        dp += __shfl_xor_sync(0xffffffffu, dp, 8);
        dp += __shfl_xor_sync(0xffffffffu, dp, 4);
        float* dst = (t < 4) ? &vbuf[4 * 1024 + t] : &dump[t];
        *dst = dp;
    }
    __syncwarp();

    // ---- epilogue: 1024 softplus terms, 32 per lane ----
    float acc = 0.0f;
#pragma unroll 4
    for (int k = 0; k < LDIM; ++k) {
        const int s = k * LDIM + t;
        const float4 v4 = *(const float4*)&vbuf[4 * (s + 1)];
        const float v   = (v4.x + v4.y) + (v4.z + v4.w);
        const float sp  = fmaxf(v, 0.0f) + __logf(1.0f + __expf(-fabsf(v)));
        acc += (sp != sp) ? -35.0f : -sp;
    }
#pragma unroll
    for (int off = 16; off > 0; off >>= 1)
        acc += __shfl_xor_sync(0xffffffffu, acc, off);

    if (t == 0) out[b] = 0.5f * acc;
}

extern "C" void kernel_launch(void* const* d_in, const int* in_sizes, int n_in,
                              void* d_out, int out_size) {
    const int*   x    = (const int*)  d_in[0];
    const float* Win  = (const float*)d_in[1];
    const float* Wc   = (const float*)d_in[2];
    const float* bc   = (const float*)d_in[3];
    const float* Wout = (const float*)d_in[4];
    const float* bout = (const float*)d_in[5];
    float* out = (float*)d_out;

    const int B = in_sizes[0] / (LDIM * LDIM);
    rnn2d_kernel<<<B, 32>>>(x, Win, Wc, bc, Wout, bout, out);
}

// round 15
// speedup vs baseline: 3.9677x; 1.0150x over previous
#include <cuda_runtime.h>
#include <math.h>
#include <stdint.h>

#define LDIM 32
#define HDIM 64

typedef unsigned long long ull;

__device__ __forceinline__ ull pack2(float lo, float hi) {
    ull r; asm("mov.b64 %0, {%1, %2};" : "=l"(r) : "f"(lo), "f"(hi)); return r;
}
__device__ __forceinline__ float2 unpack2(ull v) {
    float2 r; asm("mov.b64 {%0, %1}, %2;" : "=f"(r.x), "=f"(r.y) : "l"(v)); return r;
}
#define FMA2(d, a, b, c) \
    asm("fma.rn.f32x2 %0, %1, %2, %3;" : "=l"(d) : "l"(a), "l"(b), "l"(c))
#define ADD2(d, a, b) \
    asm("add.rn.f32x2 %0, %1, %2;" : "=l"(d) : "l"(a), "l"(b))

// One warp per sample. Thread t owns ADJACENT channels {2t, 2t+1}.
// u broadcast via double-buffered smem. NO per-step __syncwarp: the warp is
// converged through the whole step (full-mask shfls every step, zero
// divergent branches), so the warp-wide STS issues before the dependent
// warp-wide LDS and smem ops drain the LSU in order; one __syncwarp per row
// remains as a resync anchor. Win-term selects operate on packed f32x2
// pairs. Softmax: signed logit-diff partials are 3-shfl partially reduced
// and stored branch-free; all softplus/log/exp runs once in the epilogue.
__global__ void __launch_bounds__(32, 1) rnn2d_kernel(
    const int*   __restrict__ x,     // (B, 32, 32) int32, values in {0,1}
    const float* __restrict__ Win,   // (2, 64)
    const float* __restrict__ Wc,    // (64, 64)
    const float* __restrict__ bc,    // (64,)
    const float* __restrict__ Wout,  // (64, 2)
    const float* __restrict__ bout,  // (2,)
    float*       __restrict__ out)   // (B,)
{
    const int b  = blockIdx.x;
    const int t  = threadIdx.x;         // 0..31
    const int c0 = 2 * t, c1 = 2 * t + 1;

    __shared__ float2 Hprev2[LDIM][LDIM];           // [col][t] thread-private
    __shared__ __align__(16) float ubuf[2][HDIM];   // double-buffered u (channel order)
    __shared__ __align__(16) float vbuf[4 * 1025];  // 4 group partials / step
    __shared__ float dump[32];                      // sink for lanes 4..31

    // ---- weights: columns c0, c1 packed along k ----
    ull wcp0[HDIM / 2], wcp1[HDIM / 2];
#pragma unroll
    for (int k = 0; k < HDIM / 2; ++k) {
        wcp0[k] = pack2(Wc[(2 * k) * HDIM + c0], Wc[(2 * k + 1) * HDIM + c0]);
        wcp1[k] = pack2(Wc[(2 * k) * HDIM + c1], Wc[(2 * k + 1) * HDIM + c1]);
    }
    const ull winp0 = pack2(Win[c0],        Win[c1]);         // x = 0
    const ull winp1 = pack2(Win[HDIM + c0], Win[HDIM + c1]);  // x = 1
    const ull bcp   = pack2(bc[c0], bc[c1]);
    const float wod0 = Wout[c0 * 2] - Wout[c0 * 2 + 1];
    const float wod1 = Wout[c1 * 2] - Wout[c1 * 2 + 1];
    const float bodt = (t == 0) ? (bout[0] - bout[1]) : 0.0f;

#pragma unroll
    for (int c = 0; c < LDIM; ++c) Hprev2[c][t] = make_float2(0.0f, 0.0f);

    const int* xb = x + (size_t)b * LDIM * LDIM;

    float2 hp  = make_float2(0.0f, 0.0f);
    float  ppd = 0.0f;                  // deferred signed partial (step j-1)

    int xv = xb[t];                     // row 0 (this thread's column), in {0,1}

    for (int i = 0; i < LDIM; ++i) {
        const int xvNext = xb[((i < LDIM - 1) ? (i + 1) : (LDIM - 1)) * LDIM + t];
        const int dir = (i & 1) ? -1 : 1;
        const int xp  = xv;             // bit0 = current row, bit1 = previous row

        float h0 = 0.0f, h1 = 0.0f;
        int   xL = 0;

        __syncwarp();                   // per-row resync anchor

#pragma unroll 4
        for (int jj = 0; jj < LDIM; ++jj) {
            const int c = (i & 1) ? (LDIM - 1 - jj) : jj;
            const int p = jj & 1;
            const int n = i * LDIM + jj;     // global step index

            // stage u = h + carry-from-above as ONE 64-bit store
            *(ull*)&ubuf[p][c0] = pack2(h0 + hp.x, h1 + hp.y);

            // one shfl -> both current (bit0) and above (bit1) x values
            const int xs = __shfl_sync(0xffffffffu, xp, c);
            const int xC = xs & 1;
            const int xU = xs >> 1;

            // base = bc + newR @ Win, packed f32x2 selects (off the chain)
            ull rp = bcp;
            if (jj > 0) { const ull wl = xL ? winp1 : winp0; ADD2(rp, rp, wl); }
            if (i  > 0) { const ull wu = xU ? winp1 : winp0; ADD2(rp, rp, wu); }
            const float2 rr = unpack2(rp);

            // ---- partial reduction of step j-1 (3 shfls, overlaps matvec);
            //      branch-free STS: every lane stores, only lanes 0-3 land ----
            {
                float dp = ppd;
                dp += __shfl_xor_sync(0xffffffffu, dp, 16);
                dp += __shfl_xor_sync(0xffffffffu, dp, 8);
                dp += __shfl_xor_sync(0xffffffffu, dp, 4);
                float* dst = (t < 4) ? &vbuf[4 * n + t] : &dump[t];
                *dst = dp;
            }

            // ---- 64-wide matvec, packed f32x2 FMAs ----
            ull a00 = pack2(rr.x, 0.0f), a01 = 0;
            ull a10 = pack2(rr.y, 0.0f), a11 = 0;
            const ulonglong2* up = (const ulonglong2*)ubuf[p];
#pragma unroll
            for (int k = 0; k < HDIM / 4; ++k) {
                const ulonglong2 uv = up[k];
                FMA2(a00, uv.x, wcp0[2 * k],     a00);
                FMA2(a10, uv.x, wcp1[2 * k],     a10);
                FMA2(a01, uv.y, wcp0[2 * k + 1], a01);
                FMA2(a11, uv.y, wcp1[2 * k + 1], a11);
            }
            ull as0, as1;
            ADD2(as0, a00, a01);
            ADD2(as1, a10, a11);
            const float2 f0 = unpack2(as0);
            const float2 f1 = unpack2(as1);
            const float s0 = f0.x + f0.y;
            const float s1 = f1.x + f1.y;

            // elu (alpha = 1)
            const float nh0 = (s0 > 0.0f) ? s0 : (__expf(s0) - 1.0f);
            const float nh1 = (s1 > 0.0f) ? s1 : (__expf(s1) - 1.0f);

            // signed softmax partial for this step (sign = xC, bod folded)
            {
                const float base = nh0 * wod0 + nh1 * wod1 + bodt;
                ppd = xC ? base : -base;
            }

            // writeback + prefetch next carry-from-above (thread-private)
            Hprev2[c][t] = make_float2(nh0, nh1);
            const int cn = (jj < LDIM - 1) ? (c + dir) : c;  // next row: same col
            hp = Hprev2[cn][t];

            h0 = nh0;
            h1 = nh1;
            xL = xC;
        }

        // rotate rows: new packed x = next row (bit0) | this row shifted up (bit1)
        xv = xvNext | ((xp & 1) << 1);
    }

    // ---- flush the final step's partials (branch-free as well) ----
    {
        float dp = ppd;
        dp += __shfl_xor_sync(0xffffffffu, dp, 16);
        dp += __shfl_xor_sync(0xffffffffu, dp, 8);
        dp += __shfl_xor_sync(0xffffffffu, dp, 4);
        float* dst = (t < 4) ? &vbuf[4 * 1024 + t] : &dump[t];
        *dst = dp;
    }
    __syncwarp();

    // ---- epilogue: 1024 softplus terms, 32 per lane ----
    float acc = 0.0f;
#pragma unroll 4
    for (int k = 0; k < LDIM; ++k) {
        const int s = k * LDIM + t;
        const float4 v4 = *(const float4*)&vbuf[4 * (s + 1)];
        const float v   = (v4.x + v4.y) + (v4.z + v4.w);
        const float sp  = fmaxf(v, 0.0f) + __logf(1.0f + __expf(-fabsf(v)));
        acc += (sp != sp) ? -35.0f : -sp;
    }
#pragma unroll
    for (int off = 16; off > 0; off >>= 1)
        acc += __shfl_xor_sync(0xffffffffu, acc, off);

    if (t == 0) out[b] = 0.5f * acc;
}

extern "C" void kernel_launch(void* const* d_in, const int* in_sizes, int n_in,
                              void* d_out, int out_size) {
    const int*   x    = (const int*)  d_in[0];
    const float* Win  = (const float*)d_in[1];
    const float* Wc   = (const float*)d_in[2];
    const float* bc   = (const float*)d_in[3];
    const float* Wout = (const float*)d_in[4];
    const float* bout = (const float*)d_in[5];
    float* out = (float*)d_out;

    const int B = in_sizes[0] / (LDIM * LDIM);
    rnn2d_kernel<<<B, 32>>>(x, Win, Wc, bc, Wout, bout, out);
}